// round 7
// baseline (speedup 1.0000x reference)
#include <cuda_runtime.h>
#include <cuda_fp16.h>

#define NG    20000
#define BATCH 128
#define UNITS 10000
#define DEG   32

// Scratch: |feature| transposed to [gene][batch] in fp16 (5.12 MB).
// Device global array = the sanctioned allocation-free scratch.
__device__ __half g_featT[(size_t)NG * BATCH];

// ---------------------------------------------------------------------------
// Kernel 1: featT[g][b] = (half)|feature[b][g]|  — tiled transpose via SMEM.
// Reads coalesced along genes, writes coalesced along batches.
// ---------------------------------------------------------------------------
__global__ __launch_bounds__(256) void transpose_abs_kernel(const float* __restrict__ f) {
    __shared__ float tile[32][33];
    const int g0 = blockIdx.x * 32;
    const int b0 = blockIdx.y * 32;
    const int x = threadIdx.x;   // 0..31
    const int y = threadIdx.y;   // 0..7

#pragma unroll
    for (int i = 0; i < 32; i += 8) {
        int g = g0 + x;
        int b = b0 + y + i;
        float v = 0.0f;
        if (g < NG) v = fabsf(f[(size_t)b * NG + g]);
        tile[y + i][x] = v;
    }
    __syncthreads();
#pragma unroll
    for (int i = 0; i < 32; i += 8) {
        int g = g0 + y + i;
        int b = b0 + x;
        if (g < NG)
            g_featT[(size_t)g * BATCH + b] = __float2half(tile[x][y + i]);
    }
}

// ---------------------------------------------------------------------------
// Kernel 2: gather + reduce + epilogue.
// One warp per unit. Lane d holds ppi[u][d] (int32 — JAX x64-disabled
// downcasts the reference's "int64" to int32); shfl-broadcast each gene.
// Warp load of featT[g][0..127] = 256 contiguous bytes (8 B/lane, coalesced).
// Each lane accumulates 4 batches in fp32. Output staged in SMEM so the
// out[b][u] stores are coalesced.
// ---------------------------------------------------------------------------
__global__ __launch_bounds__(256) void gather_kernel(
    const int*   __restrict__ ppi,
    const float* __restrict__ kern,
    const float* __restrict__ bias,
    float*       __restrict__ out)
{
    __shared__ float so[8 * 129];   // [warp][batch], pad 129 to break bank conflicts

    const int w    = threadIdx.x >> 5;
    const int lane = threadIdx.x & 31;
    const int u    = blockIdx.x * 8 + w;   // UNITS = 10000 = 1250 * 8, always valid

    // Lane d owns index d of this unit (DEG == 32 == warp size).
    int g = __ldg(&ppi[(size_t)u * DEG + lane]);

    float a0 = 0.f, a1 = 0.f, a2 = 0.f, a3 = 0.f;
    const char* ftb = (const char*)g_featT;
    const int   lo  = lane * 8;            // byte offset within a 256B gene row

#pragma unroll
    for (int d = 0; d < DEG; d++) {
        int gd = __shfl_sync(0xffffffffu, g, d);
        uint2 raw = *(const uint2*)(ftb + (size_t)gd * (BATCH * 2) + lo);
        __half2 h0 = *(__half2*)&raw.x;
        __half2 h1 = *(__half2*)&raw.y;
        float2 f0 = __half22float2(h0);
        float2 f1 = __half22float2(h1);
        a0 += f0.x; a1 += f0.y; a2 += f1.x; a3 += f1.y;
    }

    const float k  = __ldg(&kern[u]);
    const float bi = __ldg(&bias[u]);
    const int   b0 = lane * 4;

    so[w * 129 + b0 + 0] = tanhf(fmaf(a0, k, bi));
    so[w * 129 + b0 + 1] = tanhf(fmaf(a1, k, bi));
    so[w * 129 + b0 + 2] = tanhf(fmaf(a2, k, bi));
    so[w * 129 + b0 + 3] = tanhf(fmaf(a3, k, bi));

    __syncthreads();

    // Coalesced writeback: warp covers batch rows x 8 consecutive units.
    const int u0 = blockIdx.x * 8;
#pragma unroll
    for (int i = threadIdx.x; i < BATCH * 8; i += 256) {
        int b = i >> 3;
        int j = i & 7;
        out[(size_t)b * UNITS + u0 + j] = so[j * 129 + b];
    }
}

// ---------------------------------------------------------------------------
extern "C" void kernel_launch(void* const* d_in, const int* in_sizes, int n_in,
                              void* d_out, int out_size)
{
    (void)in_sizes; (void)n_in; (void)out_size;
    const float* feature = (const float*)d_in[0];
    const int*   ppi     = (const int*)d_in[1];
    const float* kern    = (const float*)d_in[2];
    const float* bias    = (const float*)d_in[3];
    float*       out     = (float*)d_out;

    dim3 tblock(32, 8);
    dim3 tgrid((NG + 31) / 32, BATCH / 32);
    transpose_abs_kernel<<<tgrid, tblock>>>(feature);

    gather_kernel<<<UNITS / 8, 256>>>(ppi, kern, bias, out);
}